// round 13
// baseline (speedup 1.0000x reference)
#include <cuda_runtime.h>
#include <cuda_fp16.h>
#include <cstdint>

#define IN_CH   512
#define HID     16
#define OUT_CH  2
#define MAX_NODES 100000
#define DEG_BLOCKS 512

// Scratch (device globals; no allocation allowed)
__device__ __align__(16) float    g_s[MAX_NODES * 2]; // y = x@W12 (fp32)
__device__ __align__(16) unsigned g_sh[MAX_NODES];    // s = y*dinv packed half2
__device__ __align__(16) int      g_deg[MAX_NODES];   // zero-init; re-zeroed in finalize
__device__ __align__(16) float    g_dinv[MAX_NODES];  // 1/sqrt(deg+1)
__device__ __align__(16) float    g_w0[IN_CH];        // col 0 of W12 = W1@W2
__device__ __align__(16) float    g_w1[IN_CH];        // col 1 of W12
__device__ float g_c[2];                              // b1@W2 + b2

// ---------------------------------------------------------------------------
// K1: fold weights/bias (single block, 512 threads)
__global__ void prep_kernel(const float* __restrict__ W1,
                            const float* __restrict__ b1,
                            const float* __restrict__ W2,
                            const float* __restrict__ b2) {
    int t = threadIdx.x;                 // 512 threads == IN_CH
    float s0 = 0.0f, s1 = 0.0f;
#pragma unroll
    for (int h = 0; h < HID; h++) {
        float w = W1[t * HID + h];
        s0 += w * W2[h * OUT_CH + 0];
        s1 += w * W2[h * OUT_CH + 1];
    }
    g_w0[t] = s0;
    g_w1[t] = s1;
    if (t < OUT_CH) {
        float c = b2[t];
#pragma unroll
        for (int h = 0; h < HID; h++) c += b1[h] * W2[h * OUT_CH + t];
        g_c[t] = c;
    }
}

// ---------------------------------------------------------------------------
// K2: fused  deg (512 blocks, starts during prep)  ||  GEMM (PDL-syncs on prep)
__global__ void __launch_bounds__(256, 2)
fused_kernel(const float* __restrict__ x,
             const int* __restrict__ col,
             int n_edges, int n_nodes) {
    if ((int)blockIdx.x < DEG_BLOCKS) {
        int n4 = n_edges >> 2;
        int stride = DEG_BLOCKS * blockDim.x;
        for (int t = blockIdx.x * blockDim.x + threadIdx.x; t < n4; t += stride) {
            int4 c = __ldcs(reinterpret_cast<const int4*>(col) + t);
            atomicAdd(&g_deg[c.x], 1);
            atomicAdd(&g_deg[c.y], 1);
            atomicAdd(&g_deg[c.z], 1);
            atomicAdd(&g_deg[c.w], 1);
        }
        if (blockIdx.x == 0 && threadIdx.x < (n_edges & 3)) {
            atomicAdd(&g_deg[col[(n4 << 2) + threadIdx.x]], 1);
        }
        return;
    }

    cudaGridDependencySynchronize();   // GEMM consumes prep's weights

    const int lane  = threadIdx.x & 31;
    const int gwarp = (((blockIdx.x - DEG_BLOCKS) * blockDim.x) + threadIdx.x) >> 5;
    const int rbase = gwarp * 4;
    if (rbase >= n_nodes) return;

    float4 wa[4], wb[4];
#pragma unroll
    for (int j = 0; j < 4; j++) {
        int idx = lane + 32 * j;
        wa[j] = reinterpret_cast<const float4*>(g_w0)[idx];
        wb[j] = reinterpret_cast<const float4*>(g_w1)[idx];
    }

    const float4* x4 = reinterpret_cast<const float4*>(x);

    if (rbase + 4 <= n_nodes) {
        float4 v[4][4];
#pragma unroll
        for (int r = 0; r < 4; r++) {
            const float4* xr = x4 + (size_t)(rbase + r) * (IN_CH / 4);
#pragma unroll
            for (int j = 0; j < 4; j++) v[r][j] = __ldcs(xr + lane + 32 * j);
        }
        float s00 = 0.f, s01 = 0.f, s10 = 0.f, s11 = 0.f;
        float s20 = 0.f, s21 = 0.f, s30 = 0.f, s31 = 0.f;
#pragma unroll
        for (int j = 0; j < 4; j++) {
            s00 += v[0][j].x * wa[j].x + v[0][j].y * wa[j].y + v[0][j].z * wa[j].z + v[0][j].w * wa[j].w;
            s01 += v[0][j].x * wb[j].x + v[0][j].y * wb[j].y + v[0][j].z * wb[j].z + v[0][j].w * wb[j].w;
            s10 += v[1][j].x * wa[j].x + v[1][j].y * wa[j].y + v[1][j].z * wa[j].z + v[1][j].w * wa[j].w;
            s11 += v[1][j].x * wb[j].x + v[1][j].y * wb[j].y + v[1][j].z * wb[j].z + v[1][j].w * wb[j].w;
            s20 += v[2][j].x * wa[j].x + v[2][j].y * wa[j].y + v[2][j].z * wa[j].z + v[2][j].w * wa[j].w;
            s21 += v[2][j].x * wb[j].x + v[2][j].y * wb[j].y + v[2][j].z * wb[j].z + v[2][j].w * wb[j].w;
            s30 += v[3][j].x * wa[j].x + v[3][j].y * wa[j].y + v[3][j].z * wa[j].z + v[3][j].w * wa[j].w;
            s31 += v[3][j].x * wb[j].x + v[3][j].y * wb[j].y + v[3][j].z * wb[j].z + v[3][j].w * wb[j].w;
        }
#pragma unroll
        for (int off = 16; off > 0; off >>= 1) {
            s00 += __shfl_xor_sync(0xFFFFFFFFu, s00, off);
            s01 += __shfl_xor_sync(0xFFFFFFFFu, s01, off);
            s10 += __shfl_xor_sync(0xFFFFFFFFu, s10, off);
            s11 += __shfl_xor_sync(0xFFFFFFFFu, s11, off);
            s20 += __shfl_xor_sync(0xFFFFFFFFu, s20, off);
            s21 += __shfl_xor_sync(0xFFFFFFFFu, s21, off);
            s30 += __shfl_xor_sync(0xFFFFFFFFu, s30, off);
            s31 += __shfl_xor_sync(0xFFFFFFFFu, s31, off);
        }
        if (lane < 4) {
            float o0, o1;
            if      (lane == 0) { o0 = s00; o1 = s01; }
            else if (lane == 1) { o0 = s10; o1 = s11; }
            else if (lane == 2) { o0 = s20; o1 = s21; }
            else                { o0 = s30; o1 = s31; }
            reinterpret_cast<float2*>(g_s)[rbase + lane] = make_float2(o0, o1);
        }
    } else {
        for (int row = rbase; row < n_nodes; row++) {
            const float4* xr = x4 + (size_t)row * (IN_CH / 4);
            float s0 = 0.f, s1 = 0.f;
#pragma unroll
            for (int j = 0; j < 4; j++) {
                float4 v0 = __ldcs(xr + lane + 32 * j);
                s0 += v0.x * wa[j].x + v0.y * wa[j].y + v0.z * wa[j].z + v0.w * wa[j].w;
                s1 += v0.x * wb[j].x + v0.y * wb[j].y + v0.z * wb[j].z + v0.w * wb[j].w;
            }
#pragma unroll
            for (int off = 16; off > 0; off >>= 1) {
                s0 += __shfl_xor_sync(0xFFFFFFFFu, s0, off);
                s1 += __shfl_xor_sync(0xFFFFFFFFu, s1, off);
            }
            if (lane == 0)
                reinterpret_cast<float2*>(g_s)[row] = make_float2(s0, s1);
        }
    }
}

// ---------------------------------------------------------------------------
// K3: node prep (1 node/thread): dinv; s = y*dinv; out seed = s; pack half2
__global__ void nodeprep_kernel(float* __restrict__ out, int n_nodes) {
    cudaGridDependencySynchronize();
    int i = blockIdx.x * blockDim.x + threadIdx.x;
    if (i >= n_nodes) return;
    float di = rsqrtf((float)(g_deg[i] + 1));
    g_dinv[i] = di;
    float2 y = reinterpret_cast<const float2*>(g_s)[i];
    float2 s = make_float2(y.x * di, y.y * di);
    reinterpret_cast<float2*>(out)[i] = s;       // self-loop seed, fp32
    __half2 h = __floats2half2_rn(s.x, s.y);
    g_sh[i] = *reinterpret_cast<unsigned*>(&h);
}

// ---------------------------------------------------------------------------
// K4: edge scatter  out[c] += s[r]   (4 edges/thread; 4B half2 gathers)
__global__ void scatter_kernel(const int* __restrict__ row,
                               const int* __restrict__ col,
                               float* __restrict__ out, int n_edges) {
    cudaGridDependencySynchronize();
    int t = blockIdx.x * blockDim.x + threadIdx.x;
    int e = t * 4;
    if (e + 3 < n_edges) {
        int4 r = __ldg(reinterpret_cast<const int4*>(row + e));
        int4 c = __ldg(reinterpret_cast<const int4*>(col + e));

        unsigned p0 = __ldg(g_sh + r.x);
        unsigned p1 = __ldg(g_sh + r.y);
        unsigned p2 = __ldg(g_sh + r.z);
        unsigned p3 = __ldg(g_sh + r.w);
        float2 sx = __half22float2(*reinterpret_cast<__half2*>(&p0));
        float2 sy = __half22float2(*reinterpret_cast<__half2*>(&p1));
        float2 sz = __half22float2(*reinterpret_cast<__half2*>(&p2));
        float2 sw = __half22float2(*reinterpret_cast<__half2*>(&p3));

        asm volatile("red.global.add.v2.f32 [%0], {%1, %2};"
                     :: "l"(out + (size_t)c.x * 2), "f"(sx.x), "f"(sx.y) : "memory");
        asm volatile("red.global.add.v2.f32 [%0], {%1, %2};"
                     :: "l"(out + (size_t)c.y * 2), "f"(sy.x), "f"(sy.y) : "memory");
        asm volatile("red.global.add.v2.f32 [%0], {%1, %2};"
                     :: "l"(out + (size_t)c.z * 2), "f"(sz.x), "f"(sz.y) : "memory");
        asm volatile("red.global.add.v2.f32 [%0], {%1, %2};"
                     :: "l"(out + (size_t)c.w * 2), "f"(sw.x), "f"(sw.y) : "memory");
    } else {
        for (; e < n_edges; e++) {
            int r1 = row[e], c1 = col[e];
            unsigned p = __ldg(g_sh + r1);
            float2 sv = __half22float2(*reinterpret_cast<__half2*>(&p));
            asm volatile("red.global.add.v2.f32 [%0], {%1, %2};"
                         :: "l"(out + (size_t)c1 * 2), "f"(sv.x), "f"(sv.y) : "memory");
        }
    }
}

// ---------------------------------------------------------------------------
// K5: finalize (1 node/thread): out = out*dinv + c; re-zero g_deg
__global__ void finalize_kernel(float* __restrict__ out, int n_nodes) {
    cudaGridDependencySynchronize();
    int i = blockIdx.x * blockDim.x + threadIdx.x;
    if (i >= n_nodes) return;
    float c0 = g_c[0], c1 = g_c[1];
    float di = g_dinv[i];
    float2 a = reinterpret_cast<float2*>(out)[i];
    a.x = a.x * di + c0;
    a.y = a.y * di + c1;
    reinterpret_cast<float2*>(out)[i] = a;
    g_deg[i] = 0;                      // ready for next deterministic replay
}

// ---------------------------------------------------------------------------
static inline void launch_pdl(const void* fn, dim3 grid, dim3 block,
                              void** args, cudaStream_t stream) {
    cudaLaunchConfig_t cfg = {};
    cfg.gridDim = grid;
    cfg.blockDim = block;
    cfg.dynamicSmemBytes = 0;
    cfg.stream = stream;
    cudaLaunchAttribute attr[1];
    attr[0].id = cudaLaunchAttributeProgrammaticStreamSerialization;
    attr[0].val.programmaticStreamSerializationAllowed = 1;
    cfg.attrs = attr;
    cfg.numAttrs = 1;
    cudaLaunchKernelExC(&cfg, fn, args);
}

extern "C" void kernel_launch(void* const* d_in, const int* in_sizes, int n_in,
                              void* d_out, int out_size) {
    const float* x  = (const float*)d_in[0];
    const int*   ei = (const int*)d_in[1];   // [2, E]
    const float* W1 = (const float*)d_in[2];
    const float* b1 = (const float*)d_in[3];
    const float* W2 = (const float*)d_in[4];
    const float* b2 = (const float*)d_in[5];
    float* out = (float*)d_out;

    const int n_edges = in_sizes[1] / 2;
    const int n_nodes = out_size / OUT_CH;
    const int* row = ei;             // source nodes
    const int* col = ei + n_edges;   // target nodes

    const int T = 256;
    const int edge_threads = (n_edges + 3) / 4;
    const int gemm_blocks  = (n_nodes + 4 * (T / 32) - 1) / (4 * (T / 32));
    const int node_blocks  = (n_nodes + T - 1) / T;          // 1 node/thread
    const int scat_blocks  = (edge_threads + T - 1) / T;

    prep_kernel<<<1, 512>>>(W1, b1, W2, b2);

    {
        void* args[] = {(void*)&x, (void*)&col, (void*)&n_edges, (void*)&n_nodes};
        launch_pdl((const void*)fused_kernel,
                   dim3(DEG_BLOCKS + gemm_blocks), dim3(T), args, 0);
    }
    {
        void* args[] = {(void*)&out, (void*)&n_nodes};
        launch_pdl((const void*)nodeprep_kernel, dim3(node_blocks), dim3(T), args, 0);
    }
    {
        void* args[] = {(void*)&row, (void*)&col, (void*)&out, (void*)&n_edges};
        launch_pdl((const void*)scatter_kernel, dim3(scat_blocks), dim3(T), args, 0);
    }
    {
        void* args[] = {(void*)&out, (void*)&n_nodes};
        launch_pdl((const void*)finalize_kernel, dim3(node_blocks), dim3(T), args, 0);
    }
}

// round 14
// speedup vs baseline: 1.0262x; 1.0262x over previous
#include <cuda_runtime.h>
#include <cuda_fp16.h>
#include <cstdint>

#define IN_CH   512
#define HID     16
#define OUT_CH  2
#define MAX_NODES 100000
#define DEG_BLOCKS 512

// Scratch (device globals; no allocation allowed)
__device__ __align__(16) float    g_s[MAX_NODES * 2]; // y = x@W12 (fp32)
__device__ __align__(16) unsigned g_sh[MAX_NODES];    // s = y*dinv packed half2
__device__ __align__(16) int      g_deg[MAX_NODES];   // zero-init; re-zeroed in finalize
__device__ __align__(16) float    g_dinv[MAX_NODES];  // 1/sqrt(deg+1)
__device__ __align__(16) float    g_w0[IN_CH];        // col 0 of W12 = W1@W2
__device__ __align__(16) float    g_w1[IN_CH];        // col 1 of W12
__device__ float g_c[2];                              // b1@W2 + b2

// ---------------------------------------------------------------------------
// K1: fold weights/bias (single block, 512 threads)
__global__ void prep_kernel(const float* __restrict__ W1,
                            const float* __restrict__ b1,
                            const float* __restrict__ W2,
                            const float* __restrict__ b2) {
    cudaTriggerProgrammaticLaunchCompletion();   // let fused spin up now
    int t = threadIdx.x;                 // 512 threads == IN_CH
    float s0 = 0.0f, s1 = 0.0f;
#pragma unroll
    for (int h = 0; h < HID; h++) {
        float w = W1[t * HID + h];
        s0 += w * W2[h * OUT_CH + 0];
        s1 += w * W2[h * OUT_CH + 1];
    }
    g_w0[t] = s0;
    g_w1[t] = s1;
    if (t < OUT_CH) {
        float c = b2[t];
#pragma unroll
        for (int h = 0; h < HID; h++) c += b1[h] * W2[h * OUT_CH + t];
        g_c[t] = c;
    }
}

// ---------------------------------------------------------------------------
// K2: fused  deg (512 blocks, no prep dependency)  ||  GEMM (PDL-syncs on prep)
__global__ void __launch_bounds__(256, 2)
fused_kernel(const float* __restrict__ x,
             const int* __restrict__ col,
             int n_edges, int n_nodes) {
    cudaTriggerProgrammaticLaunchCompletion();   // let nodeprep spin up early

    if ((int)blockIdx.x < DEG_BLOCKS) {
        int n4 = n_edges >> 2;
        int stride = DEG_BLOCKS * blockDim.x;
        for (int t = blockIdx.x * blockDim.x + threadIdx.x; t < n4; t += stride) {
            int4 c = __ldcs(reinterpret_cast<const int4*>(col) + t);
            atomicAdd(&g_deg[c.x], 1);
            atomicAdd(&g_deg[c.y], 1);
            atomicAdd(&g_deg[c.z], 1);
            atomicAdd(&g_deg[c.w], 1);
        }
        if (blockIdx.x == 0 && threadIdx.x < (n_edges & 3)) {
            atomicAdd(&g_deg[col[(n4 << 2) + threadIdx.x]], 1);
        }
        return;
    }

    cudaGridDependencySynchronize();   // GEMM consumes prep's weights

    const int lane  = threadIdx.x & 31;
    const int gwarp = (((blockIdx.x - DEG_BLOCKS) * blockDim.x) + threadIdx.x) >> 5;
    const int rbase = gwarp * 4;
    if (rbase >= n_nodes) return;

    float4 wa[4], wb[4];
#pragma unroll
    for (int j = 0; j < 4; j++) {
        int idx = lane + 32 * j;
        wa[j] = reinterpret_cast<const float4*>(g_w0)[idx];
        wb[j] = reinterpret_cast<const float4*>(g_w1)[idx];
    }

    const float4* x4 = reinterpret_cast<const float4*>(x);

    if (rbase + 4 <= n_nodes) {
        float4 v[4][4];
#pragma unroll
        for (int r = 0; r < 4; r++) {
            const float4* xr = x4 + (size_t)(rbase + r) * (IN_CH / 4);
#pragma unroll
            for (int j = 0; j < 4; j++) v[r][j] = __ldcs(xr + lane + 32 * j);
        }
        float s00 = 0.f, s01 = 0.f, s10 = 0.f, s11 = 0.f;
        float s20 = 0.f, s21 = 0.f, s30 = 0.f, s31 = 0.f;
#pragma unroll
        for (int j = 0; j < 4; j++) {
            s00 += v[0][j].x * wa[j].x + v[0][j].y * wa[j].y + v[0][j].z * wa[j].z + v[0][j].w * wa[j].w;
            s01 += v[0][j].x * wb[j].x + v[0][j].y * wb[j].y + v[0][j].z * wb[j].z + v[0][j].w * wb[j].w;
            s10 += v[1][j].x * wa[j].x + v[1][j].y * wa[j].y + v[1][j].z * wa[j].z + v[1][j].w * wa[j].w;
            s11 += v[1][j].x * wb[j].x + v[1][j].y * wb[j].y + v[1][j].z * wb[j].z + v[1][j].w * wb[j].w;
            s20 += v[2][j].x * wa[j].x + v[2][j].y * wa[j].y + v[2][j].z * wa[j].z + v[2][j].w * wa[j].w;
            s21 += v[2][j].x * wb[j].x + v[2][j].y * wb[j].y + v[2][j].z * wb[j].z + v[2][j].w * wb[j].w;
            s30 += v[3][j].x * wa[j].x + v[3][j].y * wa[j].y + v[3][j].z * wa[j].z + v[3][j].w * wa[j].w;
            s31 += v[3][j].x * wb[j].x + v[3][j].y * wb[j].y + v[3][j].z * wb[j].z + v[3][j].w * wb[j].w;
        }
#pragma unroll
        for (int off = 16; off > 0; off >>= 1) {
            s00 += __shfl_xor_sync(0xFFFFFFFFu, s00, off);
            s01 += __shfl_xor_sync(0xFFFFFFFFu, s01, off);
            s10 += __shfl_xor_sync(0xFFFFFFFFu, s10, off);
            s11 += __shfl_xor_sync(0xFFFFFFFFu, s11, off);
            s20 += __shfl_xor_sync(0xFFFFFFFFu, s20, off);
            s21 += __shfl_xor_sync(0xFFFFFFFFu, s21, off);
            s30 += __shfl_xor_sync(0xFFFFFFFFu, s30, off);
            s31 += __shfl_xor_sync(0xFFFFFFFFu, s31, off);
        }
        if (lane < 4) {
            float o0, o1;
            if      (lane == 0) { o0 = s00; o1 = s01; }
            else if (lane == 1) { o0 = s10; o1 = s11; }
            else if (lane == 2) { o0 = s20; o1 = s21; }
            else                { o0 = s30; o1 = s31; }
            reinterpret_cast<float2*>(g_s)[rbase + lane] = make_float2(o0, o1);
        }
    } else {
        for (int row = rbase; row < n_nodes; row++) {
            const float4* xr = x4 + (size_t)row * (IN_CH / 4);
            float s0 = 0.f, s1 = 0.f;
#pragma unroll
            for (int j = 0; j < 4; j++) {
                float4 v0 = __ldcs(xr + lane + 32 * j);
                s0 += v0.x * wa[j].x + v0.y * wa[j].y + v0.z * wa[j].z + v0.w * wa[j].w;
                s1 += v0.x * wb[j].x + v0.y * wb[j].y + v0.z * wb[j].z + v0.w * wb[j].w;
            }
#pragma unroll
            for (int off = 16; off > 0; off >>= 1) {
                s0 += __shfl_xor_sync(0xFFFFFFFFu, s0, off);
                s1 += __shfl_xor_sync(0xFFFFFFFFu, s1, off);
            }
            if (lane == 0)
                reinterpret_cast<float2*>(g_s)[row] = make_float2(s0, s1);
        }
    }
}

// ---------------------------------------------------------------------------
// K3: node prep (2 nodes/thread): dinv; s = y*dinv; out seed = s; pack half2
__global__ void nodeprep_kernel(float* __restrict__ out, int n_nodes) {
    cudaTriggerProgrammaticLaunchCompletion();   // let scatter spin up early
    cudaGridDependencySynchronize();
    int i = (blockIdx.x * blockDim.x + threadIdx.x) * 2;
    if (i + 1 < n_nodes) {
        float4 y = *reinterpret_cast<float4*>(g_s + i * 2);
        float d0 = rsqrtf((float)(g_deg[i] + 1));
        float d1 = rsqrtf((float)(g_deg[i + 1] + 1));
        y.x *= d0; y.y *= d0; y.z *= d1; y.w *= d1;
        *reinterpret_cast<float4*>(out + i * 2) = y;   // self-loop seed, fp32
        __half2 h0 = __floats2half2_rn(y.x, y.y);
        __half2 h1 = __floats2half2_rn(y.z, y.w);
        uint2 p = make_uint2(*reinterpret_cast<unsigned*>(&h0),
                             *reinterpret_cast<unsigned*>(&h1));
        *reinterpret_cast<uint2*>(g_sh + i) = p;
        *reinterpret_cast<float2*>(g_dinv + i) = make_float2(d0, d1);
    } else if (i < n_nodes) {
        float di = rsqrtf((float)(g_deg[i] + 1));
        g_dinv[i] = di;
        float2 y = reinterpret_cast<const float2*>(g_s)[i];
        float2 s = make_float2(y.x * di, y.y * di);
        reinterpret_cast<float2*>(out)[i] = s;
        __half2 h = __floats2half2_rn(s.x, s.y);
        g_sh[i] = *reinterpret_cast<unsigned*>(&h);
    }
}

// ---------------------------------------------------------------------------
// K4: edge scatter  out[c] += s[r]   (4 edges/thread; 4B half2 gathers)
__global__ void scatter_kernel(const int* __restrict__ row,
                               const int* __restrict__ col,
                               float* __restrict__ out, int n_edges) {
    cudaTriggerProgrammaticLaunchCompletion();   // let finalize spin up early
    cudaGridDependencySynchronize();
    int t = blockIdx.x * blockDim.x + threadIdx.x;
    int e = t * 4;
    if (e + 3 < n_edges) {
        int4 r = __ldg(reinterpret_cast<const int4*>(row + e));
        int4 c = __ldg(reinterpret_cast<const int4*>(col + e));

        unsigned p0 = __ldg(g_sh + r.x);
        unsigned p1 = __ldg(g_sh + r.y);
        unsigned p2 = __ldg(g_sh + r.z);
        unsigned p3 = __ldg(g_sh + r.w);
        float2 sx = __half22float2(*reinterpret_cast<__half2*>(&p0));
        float2 sy = __half22float2(*reinterpret_cast<__half2*>(&p1));
        float2 sz = __half22float2(*reinterpret_cast<__half2*>(&p2));
        float2 sw = __half22float2(*reinterpret_cast<__half2*>(&p3));

        asm volatile("red.global.add.v2.f32 [%0], {%1, %2};"
                     :: "l"(out + (size_t)c.x * 2), "f"(sx.x), "f"(sx.y) : "memory");
        asm volatile("red.global.add.v2.f32 [%0], {%1, %2};"
                     :: "l"(out + (size_t)c.y * 2), "f"(sy.x), "f"(sy.y) : "memory");
        asm volatile("red.global.add.v2.f32 [%0], {%1, %2};"
                     :: "l"(out + (size_t)c.z * 2), "f"(sz.x), "f"(sz.y) : "memory");
        asm volatile("red.global.add.v2.f32 [%0], {%1, %2};"
                     :: "l"(out + (size_t)c.w * 2), "f"(sw.x), "f"(sw.y) : "memory");
    } else {
        for (; e < n_edges; e++) {
            int r1 = row[e], c1 = col[e];
            unsigned p = __ldg(g_sh + r1);
            float2 sv = __half22float2(*reinterpret_cast<__half2*>(&p));
            asm volatile("red.global.add.v2.f32 [%0], {%1, %2};"
                         :: "l"(out + (size_t)c1 * 2), "f"(sv.x), "f"(sv.y) : "memory");
        }
    }
}

// ---------------------------------------------------------------------------
// K5: finalize (2 nodes/thread): out = out*dinv + c; re-zero g_deg
__global__ void finalize_kernel(float* __restrict__ out, int n_nodes) {
    cudaGridDependencySynchronize();
    int i = (blockIdx.x * blockDim.x + threadIdx.x) * 2;
    float c0 = g_c[0], c1 = g_c[1];
    if (i + 1 < n_nodes) {
        float4 a = *reinterpret_cast<float4*>(out + i * 2);
        float2 d = *reinterpret_cast<float2*>(g_dinv + i);
        a.x = a.x * d.x + c0;  a.y = a.y * d.x + c1;
        a.z = a.z * d.y + c0;  a.w = a.w * d.y + c1;
        *reinterpret_cast<float4*>(out + i * 2) = a;
        *reinterpret_cast<int2*>(g_deg + i) = make_int2(0, 0);  // ready for next run
    } else if (i < n_nodes) {
        float di = g_dinv[i];
        float2 a = reinterpret_cast<float2*>(out)[i];
        a.x = a.x * di + c0;
        a.y = a.y * di + c1;
        reinterpret_cast<float2*>(out)[i] = a;
        g_deg[i] = 0;
    }
}

// ---------------------------------------------------------------------------
static inline void launch_pdl(const void* fn, dim3 grid, dim3 block,
                              void** args, cudaStream_t stream) {
    cudaLaunchConfig_t cfg = {};
    cfg.gridDim = grid;
    cfg.blockDim = block;
    cfg.dynamicSmemBytes = 0;
    cfg.stream = stream;
    cudaLaunchAttribute attr[1];
    attr[0].id = cudaLaunchAttributeProgrammaticStreamSerialization;
    attr[0].val.programmaticStreamSerializationAllowed = 1;
    cfg.attrs = attr;
    cfg.numAttrs = 1;
    cudaLaunchKernelExC(&cfg, fn, args);
}

extern "C" void kernel_launch(void* const* d_in, const int* in_sizes, int n_in,
                              void* d_out, int out_size) {
    const float* x  = (const float*)d_in[0];
    const int*   ei = (const int*)d_in[1];   // [2, E]
    const float* W1 = (const float*)d_in[2];
    const float* b1 = (const float*)d_in[3];
    const float* W2 = (const float*)d_in[4];
    const float* b2 = (const float*)d_in[5];
    float* out = (float*)d_out;

    const int n_edges = in_sizes[1] / 2;
    const int n_nodes = out_size / OUT_CH;
    const int* row = ei;             // source nodes
    const int* col = ei + n_edges;   // target nodes

    const int T = 256;
    const int edge_threads = (n_edges + 3) / 4;
    const int gemm_blocks  = (n_nodes + 4 * (T / 32) - 1) / (4 * (T / 32));
    const int node2_blocks = ((n_nodes + 1) / 2 + T - 1) / T;
    const int scat_blocks  = (edge_threads + T - 1) / T;

    prep_kernel<<<1, 512>>>(W1, b1, W2, b2);

    {
        void* args[] = {(void*)&x, (void*)&col, (void*)&n_edges, (void*)&n_nodes};
        launch_pdl((const void*)fused_kernel,
                   dim3(DEG_BLOCKS + gemm_blocks), dim3(T), args, 0);
    }
    {
        void* args[] = {(void*)&out, (void*)&n_nodes};
        launch_pdl((const void*)nodeprep_kernel, dim3(node2_blocks), dim3(T), args, 0);
    }
    {
        void* args[] = {(void*)&row, (void*)&col, (void*)&out, (void*)&n_edges};
        launch_pdl((const void*)scatter_kernel, dim3(scat_blocks), dim3(T), args, 0);
    }
    {
        void* args[] = {(void*)&out, (void*)&n_nodes};
        launch_pdl((const void*)finalize_kernel, dim3(node2_blocks), dim3(T), args, 0);
    }
}